// round 1
// baseline (speedup 1.0000x reference)
#include <cuda_runtime.h>
#include <math.h>

#define Bb 16
#define Cc 512
#define Hh 32
#define Ww 32
#define Nn 16384
#define Dd 32
#define Pp 16384   // Bb*Hh*Ww

// Scratch (allocation-free rule: __device__ globals)
__device__ float g_z[Pp * Dd];       // normalized projected latents, [p][d]
__device__ float g_e[Nn * Dd];       // normalized codebook, [n][d]
__device__ int   g_idx[Pp];          // argmax code per position
__device__ int   g_hist[Nn];         // usage histogram
__device__ float g_loss_part[512];   // per-(b,h) loss partials

// ---------------------------------------------------------------------------
// K_zero: clear histogram (graph replays must be idempotent)
// ---------------------------------------------------------------------------
__global__ void k_zero_hist() {
    g_hist[blockIdx.x * 256 + threadIdx.x] = 0;
}

// ---------------------------------------------------------------------------
// K0: normalize codebook rows. One warp per row.
// ---------------------------------------------------------------------------
__global__ void k_norm_e(const float* __restrict__ emb) {
    int warp = threadIdx.x >> 5, lane = threadIdx.x & 31;
    int r = blockIdx.x * 8 + warp;
    float v = emb[r * Dd + lane];
    float ss = v * v;
    #pragma unroll
    for (int o = 16; o; o >>= 1) ss += __shfl_xor_sync(0xffffffffu, ss, o);
    float rn = 1.0f / fmaxf(sqrtf(ss), 1e-6f);
    g_e[r * Dd + lane] = v * rn;
}

// ---------------------------------------------------------------------------
// K1: projection (1x1 conv C->D) + L2 normalize along D.
// One block per (b,h): 32 positions (w), D=32 outputs.
// ---------------------------------------------------------------------------
__global__ __launch_bounds__(256) void k_project(const float* __restrict__ enc,
                                                 const float* __restrict__ pw,
                                                 const float* __restrict__ pb) {
    __shared__ float enc_s[64][32];
    __shared__ float proj_s[32][64];
    __shared__ float z_s[32][33];
    __shared__ float rn_s[32];

    int bh  = blockIdx.x;               // b*32 + h
    int tid = threadIdx.x;
    int w   = tid & 31;
    int dg  = tid >> 5;                 // 0..7

    const float* encbase = enc + (size_t)(bh >> 5) * Cc * Hh * Ww + (size_t)(bh & 31) * Ww;

    float acc[4] = {0.f, 0.f, 0.f, 0.f};

    for (int c0 = 0; c0 < Cc; c0 += 64) {
        for (int i = tid; i < 64 * 32; i += 256) {
            int cl = i >> 5, ww = i & 31;
            enc_s[cl][ww] = encbase[(size_t)(c0 + cl) * (Hh * Ww) + ww];
        }
        for (int i = tid; i < 32 * 64; i += 256) {
            int d = i >> 6, cl = i & 63;
            proj_s[d][cl] = pw[d * Cc + c0 + cl];
        }
        __syncthreads();
        #pragma unroll 16
        for (int cl = 0; cl < 64; cl++) {
            float ev = enc_s[cl][w];
            #pragma unroll
            for (int j = 0; j < 4; j++) acc[j] += proj_s[dg + 8 * j][cl] * ev;
        }
        __syncthreads();
    }
    #pragma unroll
    for (int j = 0; j < 4; j++) z_s[dg + 8 * j][w] = acc[j] + pb[dg + 8 * j];
    __syncthreads();

    if (tid < 32) {
        float ss = 0.f;
        #pragma unroll
        for (int d = 0; d < 32; d++) { float v = z_s[d][tid]; ss += v * v; }
        rn_s[tid] = 1.0f / fmaxf(sqrtf(ss), 1e-6f);
    }
    __syncthreads();

    for (int i = tid; i < 1024; i += 256) {
        int ww = i >> 5, d = i & 31;
        g_z[((size_t)bh * 32 + ww) * Dd + d] = z_s[d][ww] * rn_s[ww];
    }
}

// ---------------------------------------------------------------------------
// K2: fused sims GEMM (P x N x D) + running argmax + histogram.
// Block: 64 positions. Thread: 8 positions x 4 codes. Code tile = 128.
// Warp = one position-group (pg) -> z loads are warp-uniform broadcasts.
// ---------------------------------------------------------------------------
__global__ __launch_bounds__(256) void k_argmax() {
    __shared__ __align__(16) float z_s[64][32];
    __shared__ __align__(16) float e_s[32][132];   // 132-float row stride: 16B-aligned rows, conflict-free float4

    int tid = threadIdx.x;
    int pg  = tid >> 5;     // warp id: position group, 8 positions each
    int cg  = tid & 31;     // lane: code group, 4 codes each

    int pbase = blockIdx.x * 64;

    for (int i = tid; i < 64 * 32; i += 256)
        z_s[i >> 5][i & 31] = g_z[(size_t)pbase * Dd + i];

    float best[8];
    int   bidx[8];
    #pragma unroll
    for (int j = 0; j < 8; j++) { best[j] = -1e30f; bidx[j] = 0; }

    for (int cb = 0; cb < Nn; cb += 128) {
        __syncthreads();   // protects z_s (first iter) and e_s reuse
        for (int i = tid; i < 128 * 32; i += 256) {
            int c = i >> 5, k = i & 31;
            e_s[k][c] = g_e[(size_t)(cb + c) * Dd + k];
        }
        __syncthreads();

        float acc[8][4];
        #pragma unroll
        for (int j = 0; j < 8; j++)
            #pragma unroll
            for (int i = 0; i < 4; i++) acc[j][i] = 0.f;

        #pragma unroll 8
        for (int k = 0; k < 32; k++) {
            float4 ev = *(const float4*)&e_s[k][4 * cg];
            #pragma unroll
            for (int j = 0; j < 8; j++) {
                float zv = z_s[8 * pg + j][k];     // warp-uniform broadcast
                acc[j][0] += zv * ev.x;
                acc[j][1] += zv * ev.y;
                acc[j][2] += zv * ev.z;
                acc[j][3] += zv * ev.w;
            }
        }

        #pragma unroll
        for (int j = 0; j < 8; j++) {
            #pragma unroll
            for (int i = 0; i < 4; i++) {
                int cid = cb + 4 * cg + i;
                if (acc[j][i] > best[j]) { best[j] = acc[j][i]; bidx[j] = cid; }
            }
        }
    }

    // reduce (val, idx) across the warp; first-occurrence tie-break like argmax
    #pragma unroll
    for (int j = 0; j < 8; j++) {
        float v = best[j]; int ix = bidx[j];
        #pragma unroll
        for (int o = 16; o; o >>= 1) {
            float ov = __shfl_xor_sync(0xffffffffu, v, o);
            int   oi = __shfl_xor_sync(0xffffffffu, ix, o);
            if (ov > v || (ov == v && oi < ix)) { v = ov; ix = oi; }
        }
        if (cg == 0) {
            g_idx[pbase + 8 * pg + j] = ix;
            atomicAdd(&g_hist[ix], 1);
        }
    }
}

// ---------------------------------------------------------------------------
// K3: gather latents, quantization-loss partial, expand D->C, write out.
// One block per (b,h).
// ---------------------------------------------------------------------------
__global__ __launch_bounds__(256) void k_output(const float* __restrict__ ew,
                                                const float* __restrict__ eb,
                                                float* __restrict__ out) {
    __shared__ float lat_s[32][33];
    __shared__ float exp_s[64][32];
    __shared__ float red[256];

    int bh  = blockIdx.x;
    int b   = bh >> 5, h = bh & 31;
    int tid = threadIdx.x;
    int pbase = bh * 32;

    float lsum = 0.f;
    for (int i = tid; i < 1024; i += 256) {
        int ww = i >> 5, d = i & 31;
        int ix = g_idx[pbase + ww];
        float lv = g_e[(size_t)ix * Dd + d];
        lat_s[ww][d] = lv;
        float dz = g_z[((size_t)pbase + ww) * Dd + d] - lv;
        lsum += dz * dz;
    }
    red[tid] = lsum;
    __syncthreads();
    for (int s = 128; s; s >>= 1) {
        if (tid < s) red[tid] += red[tid + s];
        __syncthreads();
    }
    if (tid == 0) g_loss_part[bh] = red[0];

    int w   = tid & 31;
    int cg8 = tid >> 5;

    for (int c0 = 0; c0 < Cc; c0 += 64) {
        __syncthreads();
        for (int i = tid; i < 64 * 32; i += 256) {
            int cl = i >> 5, d = i & 31;
            exp_s[cl][d] = ew[(size_t)(c0 + cl) * Dd + d];
        }
        __syncthreads();
        #pragma unroll
        for (int jj = 0; jj < 8; jj++) {
            int cl = cg8 + 8 * jj;
            int c  = c0 + cl;
            float s = eb[c];
            #pragma unroll
            for (int d = 0; d < 32; d++) s += exp_s[cl][d] * lat_s[w][d];
            out[(((size_t)b * Cc + c) * Hh + h) * Ww + w] = s;
        }
    }
}

// ---------------------------------------------------------------------------
// K4: final scalars — loss mean and perplexity — deterministic reductions.
// ---------------------------------------------------------------------------
__global__ void k_scalars(float* __restrict__ out, int osz) {
    __shared__ float red[256];
    int tid = threadIdx.x;

    float s = 0.f;
    for (int i = tid; i < 512; i += 256) s += g_loss_part[i];
    red[tid] = s;
    __syncthreads();
    for (int st = 128; st; st >>= 1) {
        if (tid < st) red[tid] += red[tid + st];
        __syncthreads();
    }
    if (tid == 0) out[osz - 2] = red[0] / (float)(Pp * Dd);
    __syncthreads();

    float e = 0.f;
    const float inv = 1.0f / (float)Pp;
    for (int i = tid; i < Nn; i += 256) {
        int c = g_hist[i];
        if (c > 0) {
            float u = (float)c * inv;
            e -= u * logf(u + 1e-6f);
        }
    }
    red[tid] = e;
    __syncthreads();
    for (int st = 128; st; st >>= 1) {
        if (tid < st) red[tid] += red[tid + st];
        __syncthreads();
    }
    if (tid == 0) out[osz - 1] = expf(red[0]);
}

// ---------------------------------------------------------------------------
extern "C" void kernel_launch(void* const* d_in, const int* in_sizes, int n_in,
                              void* d_out, int out_size) {
    const float* enc = (const float*)d_in[0];   // encodings [B,C,H,W]
    const float* emb = (const float*)d_in[1];   // emb_weight [N,D]
    const float* pw  = (const float*)d_in[2];   // proj_w [D,C]
    const float* pb  = (const float*)d_in[3];   // proj_b [D]
    const float* ew  = (const float*)d_in[4];   // exp_w [C,D]
    const float* eb  = (const float*)d_in[5];   // exp_b [C]
    float* out = (float*)d_out;

    k_zero_hist<<<Nn / 256, 256>>>();
    k_norm_e<<<Nn / 8, 256>>>(emb);
    k_project<<<Bb * Hh, 256>>>(enc, pw, pb);
    k_argmax<<<Pp / 64, 256>>>();
    k_output<<<Bb * Hh, 256>>>(ew, eb, out);
    k_scalars<<<1, 256>>>(out, out_size);
}

// round 2
// speedup vs baseline: 1.0425x; 1.0425x over previous
#include <cuda_runtime.h>
#include <math.h>

#define Bb 16
#define Cc 512
#define Hh 32
#define Ww 32
#define Nn 16384
#define Dd 32
#define Pp 16384   // Bb*Hh*Ww

// Scratch (allocation-free rule: __device__ globals)
__device__ float g_z[Pp * Dd];       // normalized projected latents, [p][d]
__device__ float g_e[Nn * Dd];       // normalized codebook, [n][d]
__device__ int   g_idx[Pp];          // argmax code per position
__device__ int   g_hist[Nn];         // usage histogram
__device__ float g_loss_part[512];   // per-(b,h) loss partials

// packed fp32x2 helpers ------------------------------------------------------
__device__ __forceinline__ unsigned long long ffma2(unsigned long long a,
                                                    unsigned long long b,
                                                    unsigned long long c) {
    unsigned long long d;
    asm("fma.rn.f32x2 %0, %1, %2, %3;" : "=l"(d) : "l"(a), "l"(b), "l"(c));
    return d;
}
__device__ __forceinline__ unsigned long long packdup(float v) {
    unsigned long long r;
    asm("mov.b64 %0, {%1, %1};" : "=l"(r) : "r"(__float_as_uint(v)));
    return r;
}

// ---------------------------------------------------------------------------
// K_zero: clear histogram (graph replays must be idempotent)
// ---------------------------------------------------------------------------
__global__ void k_zero_hist() {
    g_hist[blockIdx.x * 256 + threadIdx.x] = 0;
}

// ---------------------------------------------------------------------------
// K0: normalize codebook rows. One warp per row.
// ---------------------------------------------------------------------------
__global__ void k_norm_e(const float* __restrict__ emb) {
    int warp = threadIdx.x >> 5, lane = threadIdx.x & 31;
    int r = blockIdx.x * 8 + warp;
    float v = emb[r * Dd + lane];
    float ss = v * v;
    #pragma unroll
    for (int o = 16; o; o >>= 1) ss += __shfl_xor_sync(0xffffffffu, ss, o);
    float rn = 1.0f / fmaxf(sqrtf(ss), 1e-6f);
    g_e[r * Dd + lane] = v * rn;
}

// ---------------------------------------------------------------------------
// K1: projection (1x1 conv C->D) + L2 normalize along D.
// ---------------------------------------------------------------------------
__global__ __launch_bounds__(256) void k_project(const float* __restrict__ enc,
                                                 const float* __restrict__ pw,
                                                 const float* __restrict__ pb) {
    __shared__ float enc_s[64][32];
    __shared__ float proj_s[32][64];
    __shared__ float z_s[32][33];
    __shared__ float rn_s[32];

    int bh  = blockIdx.x;
    int tid = threadIdx.x;
    int w   = tid & 31;
    int dg  = tid >> 5;

    const float* encbase = enc + (size_t)(bh >> 5) * Cc * Hh * Ww + (size_t)(bh & 31) * Ww;

    float acc[4] = {0.f, 0.f, 0.f, 0.f};

    for (int c0 = 0; c0 < Cc; c0 += 64) {
        for (int i = tid; i < 64 * 32; i += 256) {
            int cl = i >> 5, ww = i & 31;
            enc_s[cl][ww] = encbase[(size_t)(c0 + cl) * (Hh * Ww) + ww];
        }
        for (int i = tid; i < 32 * 64; i += 256) {
            int d = i >> 6, cl = i & 63;
            proj_s[d][cl] = pw[d * Cc + c0 + cl];
        }
        __syncthreads();
        #pragma unroll 16
        for (int cl = 0; cl < 64; cl++) {
            float ev = enc_s[cl][w];
            #pragma unroll
            for (int j = 0; j < 4; j++) acc[j] += proj_s[dg + 8 * j][cl] * ev;
        }
        __syncthreads();
    }
    #pragma unroll
    for (int j = 0; j < 4; j++) z_s[dg + 8 * j][w] = acc[j] + pb[dg + 8 * j];
    __syncthreads();

    if (tid < 32) {
        float ss = 0.f;
        #pragma unroll
        for (int d = 0; d < 32; d++) { float v = z_s[d][tid]; ss += v * v; }
        rn_s[tid] = 1.0f / fmaxf(sqrtf(ss), 1e-6f);
    }
    __syncthreads();

    for (int i = tid; i < 1024; i += 256) {
        int ww = i >> 5, d = i & 31;
        g_z[((size_t)bh * 32 + ww) * Dd + d] = z_s[d][ww] * rn_s[ww];
    }
}

// ---------------------------------------------------------------------------
// K2: fused sims GEMM (P x N x D) + running argmax + histogram.
// FFMA2 (fma.rn.f32x2): accumulators pair ADJACENT POSITIONS in one b64 reg.
// z stored transposed [d][pos] so LDS.64 yields a packed position pair.
// Thread: 4 pos-pairs (8 positions) x 4 codes = 16 packed accumulators.
// ---------------------------------------------------------------------------
__global__ __launch_bounds__(256) void k_argmax() {
    __shared__ __align__(16) float z_s[32][64];    // [d][pos]
    __shared__ __align__(16) float e_s[32][132];   // [d][code], padded

    int tid = threadIdx.x;
    int pg  = tid >> 5;     // warp id: position group (8 positions)
    int cg  = tid & 31;     // lane: code group (4 codes)
    int pbase = blockIdx.x * 64;

    // fill z transposed; i = d*64 + p  -> conflict-free STS
    for (int i = tid; i < 64 * 32; i += 256) {
        int p = i & 63, d = i >> 6;
        z_s[d][p] = g_z[(size_t)(pbase + p) * Dd + d];
    }

    float best[8];
    int   bidx[8];
    #pragma unroll
    for (int j = 0; j < 8; j++) { best[j] = -1e30f; bidx[j] = 0; }

    for (int cb = 0; cb < Nn; cb += 128) {
        __syncthreads();   // protects z_s (first iter) and e_s reuse
        // coalesced gmem read; 4-way-conflict STS (cheap vs inner loop)
        for (int i = tid; i < 128 * 32; i += 256) {
            int c = i >> 5, k = i & 31;
            e_s[k][c] = g_e[(size_t)(cb + c) * Dd + k];
        }
        __syncthreads();

        unsigned long long acc[4][4];
        #pragma unroll
        for (int j = 0; j < 4; j++)
            #pragma unroll
            for (int i = 0; i < 4; i++) acc[j][i] = 0ull;   // (0.f, 0.f)

        #pragma unroll 8
        for (int k = 0; k < 32; k++) {
            float4 ev = *(const float4*)&e_s[k][4 * cg];
            unsigned long long e0 = packdup(ev.x);
            unsigned long long e1 = packdup(ev.y);
            unsigned long long e2 = packdup(ev.z);
            unsigned long long e3 = packdup(ev.w);
            #pragma unroll
            for (int j = 0; j < 4; j++) {
                // packed (z[p], z[p+1]) — warp-uniform broadcast LDS.64
                unsigned long long zz =
                    *(const unsigned long long*)&z_s[k][8 * pg + 2 * j];
                acc[j][0] = ffma2(zz, e0, acc[j][0]);
                acc[j][1] = ffma2(zz, e1, acc[j][1]);
                acc[j][2] = ffma2(zz, e2, acc[j][2]);
                acc[j][3] = ffma2(zz, e3, acc[j][3]);
            }
        }

        #pragma unroll
        for (int j = 0; j < 4; j++) {
            #pragma unroll
            for (int i = 0; i < 4; i++) {
                unsigned int lo_u, hi_u;
                asm("mov.b64 {%0, %1}, %2;" : "=r"(lo_u), "=r"(hi_u) : "l"(acc[j][i]));
                float lo = __uint_as_float(lo_u);
                float hi = __uint_as_float(hi_u);
                int cid = cb + 4 * cg + i;
                if (lo > best[2 * j])     { best[2 * j] = lo;     bidx[2 * j] = cid; }
                if (hi > best[2 * j + 1]) { best[2 * j + 1] = hi; bidx[2 * j + 1] = cid; }
            }
        }
    }

    // reduce (val, idx) across the warp; first-occurrence tie-break
    #pragma unroll
    for (int j = 0; j < 8; j++) {
        float v = best[j]; int ix = bidx[j];
        #pragma unroll
        for (int o = 16; o; o >>= 1) {
            float ov = __shfl_xor_sync(0xffffffffu, v, o);
            int   oi = __shfl_xor_sync(0xffffffffu, ix, o);
            if (ov > v || (ov == v && oi < ix)) { v = ov; ix = oi; }
        }
        if (cg == 0) {
            g_idx[pbase + 8 * pg + j] = ix;   // position 8*pg + j
            atomicAdd(&g_hist[ix], 1);
        }
    }
}

// ---------------------------------------------------------------------------
// K3: gather latents, quantization-loss partial, expand D->C, write out.
// ---------------------------------------------------------------------------
__global__ __launch_bounds__(256) void k_output(const float* __restrict__ ew,
                                                const float* __restrict__ eb,
                                                float* __restrict__ out) {
    __shared__ float lat_s[32][33];
    __shared__ float exp_s[64][32];
    __shared__ float red[256];

    int bh  = blockIdx.x;
    int b   = bh >> 5, h = bh & 31;
    int tid = threadIdx.x;
    int pbase = bh * 32;

    float lsum = 0.f;
    for (int i = tid; i < 1024; i += 256) {
        int ww = i >> 5, d = i & 31;
        int ix = g_idx[pbase + ww];
        float lv = g_e[(size_t)ix * Dd + d];
        lat_s[ww][d] = lv;
        float dz = g_z[((size_t)pbase + ww) * Dd + d] - lv;
        lsum += dz * dz;
    }
    red[tid] = lsum;
    __syncthreads();
    for (int s = 128; s; s >>= 1) {
        if (tid < s) red[tid] += red[tid + s];
        __syncthreads();
    }
    if (tid == 0) g_loss_part[bh] = red[0];

    int w   = tid & 31;
    int cg8 = tid >> 5;

    for (int c0 = 0; c0 < Cc; c0 += 64) {
        __syncthreads();
        for (int i = tid; i < 64 * 32; i += 256) {
            int cl = i >> 5, d = i & 31;
            exp_s[cl][d] = ew[(size_t)(c0 + cl) * Dd + d];
        }
        __syncthreads();
        #pragma unroll
        for (int jj = 0; jj < 8; jj++) {
            int cl = cg8 + 8 * jj;
            int c  = c0 + cl;
            float s = eb[c];
            #pragma unroll
            for (int d = 0; d < 32; d++) s += exp_s[cl][d] * lat_s[w][d];
            out[(((size_t)b * Cc + c) * Hh + h) * Ww + w] = s;
        }
    }
}

// ---------------------------------------------------------------------------
// K4: final scalars — loss mean and perplexity.
// ---------------------------------------------------------------------------
__global__ void k_scalars(float* __restrict__ out, int osz) {
    __shared__ float red[256];
    int tid = threadIdx.x;

    float s = 0.f;
    for (int i = tid; i < 512; i += 256) s += g_loss_part[i];
    red[tid] = s;
    __syncthreads();
    for (int st = 128; st; st >>= 1) {
        if (tid < st) red[tid] += red[tid + st];
        __syncthreads();
    }
    if (tid == 0) out[osz - 2] = red[0] / (float)(Pp * Dd);
    __syncthreads();

    float e = 0.f;
    const float inv = 1.0f / (float)Pp;
    for (int i = tid; i < Nn; i += 256) {
        int c = g_hist[i];
        if (c > 0) {
            float u = (float)c * inv;
            e -= u * logf(u + 1e-6f);
        }
    }
    red[tid] = e;
    __syncthreads();
    for (int st = 128; st; st >>= 1) {
        if (tid < st) red[tid] += red[tid + st];
        __syncthreads();
    }
    if (tid == 0) out[osz - 1] = expf(red[0]);
}

// ---------------------------------------------------------------------------
extern "C" void kernel_launch(void* const* d_in, const int* in_sizes, int n_in,
                              void* d_out, int out_size) {
    const float* enc = (const float*)d_in[0];   // encodings [B,C,H,W]
    const float* emb = (const float*)d_in[1];   // emb_weight [N,D]
    const float* pw  = (const float*)d_in[2];   // proj_w [D,C]
    const float* pb  = (const float*)d_in[3];   // proj_b [D]
    const float* ew  = (const float*)d_in[4];   // exp_w [C,D]
    const float* eb  = (const float*)d_in[5];   // exp_b [C]
    float* out = (float*)d_out;

    k_zero_hist<<<Nn / 256, 256>>>();
    k_norm_e<<<Nn / 8, 256>>>(emb);
    k_project<<<Bb * Hh, 256>>>(enc, pw, pb);
    k_argmax<<<Pp / 64, 256>>>();
    k_output<<<Bb * Hh, 256>>>(ew, eb, out);
    k_scalars<<<1, 256>>>(out, out_size);
}

// round 4
// speedup vs baseline: 1.2031x; 1.1541x over previous
#include <cuda_runtime.h>
#include <cuda_bf16.h>
#include <math.h>
#include <cstdint>

#define Bb 16
#define Cc 512
#define Hh 32
#define Ww 32
#define Nn 16384
#define Dd 32
#define Pp 16384   // Bb*Hh*Ww

// ---------------------------------------------------------------------------
// Scratch (__device__ globals; no allocation allowed)
// ---------------------------------------------------------------------------
__device__ float g_z[Pp * Dd];       // normalized projected latents [p][d]
__device__ float g_e[Nn * Dd];       // normalized codebook fp32 [n][d]
__device__ uint4 g_eb[Nn * 12];      // codebook bf16 split: [n][96 bf16] = [hi|mid|hi]
__device__ int2  g_top[Pp];          // top-2 candidate code ids per position
__device__ int   g_idx[Pp];
__device__ int   g_hist[Nn];
__device__ float g_loss_part[512];

// ---------------------------------------------------------------------------
// PTX helpers (baseline PTX only: no 'a'-features)
// ---------------------------------------------------------------------------
__device__ __forceinline__ uint32_t smem_u32(const void* p) {
    uint32_t a;
    asm("{ .reg .u64 t; cvta.to.shared.u64 t, %1; cvt.u32.u64 %0, t; }" : "=r"(a) : "l"(p));
    return a;
}
__device__ __forceinline__ void ldsm4(uint32_t* r, uint32_t addr) {
    asm volatile("ldmatrix.sync.aligned.m8n8.x4.shared.b16 {%0,%1,%2,%3}, [%4];"
                 : "=r"(r[0]), "=r"(r[1]), "=r"(r[2]), "=r"(r[3]) : "r"(addr));
}
__device__ __forceinline__ void mma16816(float* d, const uint32_t* a, const uint32_t* b) {
    asm volatile("mma.sync.aligned.m16n8k16.row.col.f32.bf16.bf16.f32 "
                 "{%0,%1,%2,%3}, {%4,%5,%6,%7}, {%8,%9}, {%0,%1,%2,%3};"
                 : "+f"(d[0]), "+f"(d[1]), "+f"(d[2]), "+f"(d[3])
                 : "r"(a[0]), "r"(a[1]), "r"(a[2]), "r"(a[3]), "r"(b[0]), "r"(b[1]));
}
__device__ __forceinline__ void cpasync16(uint32_t dst, const void* src) {
    asm volatile("cp.async.cg.shared.global [%0], [%1], 16;" :: "r"(dst), "l"(src));
}
#define CP_COMMIT() asm volatile("cp.async.commit_group;" ::: "memory")
#define CP_WAIT0()  asm volatile("cp.async.wait_group 0;" ::: "memory")

__device__ __forceinline__ bool better(float xv, int xi, float yv, int yi) {
    return xv > yv || (xv == yv && xi < yi);
}

// ---------------------------------------------------------------------------
// K_zero: clear histogram
// ---------------------------------------------------------------------------
__global__ void k_zero_hist() {
    g_hist[blockIdx.x * 256 + threadIdx.x] = 0;
}

// ---------------------------------------------------------------------------
// K_prep_e: normalize codebook rows; fp32 copy + bf16 split [hi|mid|hi].
// One warp per code.
// ---------------------------------------------------------------------------
__global__ void k_prep_e(const float* __restrict__ emb) {
    int warp = threadIdx.x >> 5, lane = threadIdx.x & 31;
    int n = blockIdx.x * 8 + warp;
    float v = emb[n * Dd + lane];
    float ss = v * v;
    #pragma unroll
    for (int o = 16; o; o >>= 1) ss += __shfl_xor_sync(0xffffffffu, ss, o);
    float rn = 1.0f / fmaxf(sqrtf(ss), 1e-6f);
    float zn = v * rn;
    g_e[n * Dd + lane] = zn;

    __nv_bfloat16 h = __float2bfloat16(zn);
    __nv_bfloat16 m = __float2bfloat16(zn - __bfloat162float(h));
    __nv_bfloat16* gb = (__nv_bfloat16*)g_eb + (size_t)n * 96 + lane;
    gb[0]  = h;    // k-block 0: e_hi
    gb[32] = m;    // k-block 1: e_mid
    gb[64] = h;    // k-block 2: e_hi
}

// ---------------------------------------------------------------------------
// K1: projection (1x1 conv C->D) + L2 normalize along D.
// ---------------------------------------------------------------------------
__global__ __launch_bounds__(256) void k_project(const float* __restrict__ enc,
                                                 const float* __restrict__ pw,
                                                 const float* __restrict__ pb) {
    __shared__ float enc_s[64][32];
    __shared__ float proj_s[32][64];
    __shared__ float z_s[32][33];
    __shared__ float rn_s[32];

    int bh  = blockIdx.x;
    int tid = threadIdx.x;
    int w   = tid & 31;
    int dg  = tid >> 5;

    const float* encbase = enc + (size_t)(bh >> 5) * Cc * Hh * Ww + (size_t)(bh & 31) * Ww;

    float acc[4] = {0.f, 0.f, 0.f, 0.f};

    for (int c0 = 0; c0 < Cc; c0 += 64) {
        for (int i = tid; i < 64 * 32; i += 256) {
            int cl = i >> 5, ww = i & 31;
            enc_s[cl][ww] = encbase[(size_t)(c0 + cl) * (Hh * Ww) + ww];
        }
        for (int i = tid; i < 32 * 64; i += 256) {
            int d = i >> 6, cl = i & 63;
            proj_s[d][cl] = pw[d * Cc + c0 + cl];
        }
        __syncthreads();
        #pragma unroll 16
        for (int cl = 0; cl < 64; cl++) {
            float ev = enc_s[cl][w];
            #pragma unroll
            for (int j = 0; j < 4; j++) acc[j] += proj_s[dg + 8 * j][cl] * ev;
        }
        __syncthreads();
    }
    #pragma unroll
    for (int j = 0; j < 4; j++) z_s[dg + 8 * j][w] = acc[j] + pb[dg + 8 * j];
    __syncthreads();

    if (tid < 32) {
        float ss = 0.f;
        #pragma unroll
        for (int d = 0; d < 32; d++) { float v = z_s[d][tid]; ss += v * v; }
        rn_s[tid] = 1.0f / fmaxf(sqrtf(ss), 1e-6f);
    }
    __syncthreads();

    for (int i = tid; i < 1024; i += 256) {
        int ww = i >> 5, d = i & 31;
        g_z[((size_t)bh * 32 + ww) * Dd + d] = z_s[d][ww] * rn_s[ww];
    }
}

// ---------------------------------------------------------------------------
// K2: HMMA sims (bf16 3-split, K=96) + running top-2 per position.
// CTA: 512 threads (16 warps), 128 positions. Code tile = 64, 256 iters.
// Warp (w&7): row group (16 pos); (w>>3): n-half (32 codes of the tile).
// SMEM: A 128x104 bf16 (26624 B); B double buffer 2 x 64x104 bf16 (13312 B).
// ---------------------------------------------------------------------------
#define A_BYTES   26624
#define B_BYTES   13312
#define SIMS_SMEM (A_BYTES + 2 * B_BYTES)   // 53248

__global__ __launch_bounds__(512, 1) void k_sims() {
    extern __shared__ __align__(16) char sm[];
    __nv_bfloat16* As = (__nv_bfloat16*)sm;     // stride 104 bf16 = 208 B
    uint32_t sbase = smem_u32(sm);

    int tid  = threadIdx.x;
    int lane = tid & 31;
    int w    = tid >> 5;
    int nh   = w >> 3;        // n-half
    int tg   = lane & 3;
    int gr   = lane >> 2;     // row-in-group 0..7
    int pbase = blockIdx.x * 128;

    // ---- build A tile: [hi | hi | mid] per row ----
    for (int i = tid; i < 128 * 32; i += 512) {
        int row = i >> 5, d = i & 31;
        float z = g_z[(size_t)(pbase + row) * Dd + d];
        __nv_bfloat16 h = __float2bfloat16(z);
        __nv_bfloat16 m = __float2bfloat16(z - __bfloat162float(h));
        As[row * 104 + d]      = h;
        As[row * 104 + 32 + d] = h;
        As[row * 104 + 64 + d] = m;
    }

    // ---- prefetch B tile 0 ----
    const char* ebase = (const char*)g_eb;
    for (int ci = tid; ci < 768; ci += 512)
        cpasync16(sbase + A_BYTES + (ci / 12) * 208 + (ci % 12) * 16,
                  ebase + (ci / 12) * 192 + (ci % 12) * 16);
    CP_COMMIT();
    __syncthreads();

    // ---- A fragments (all 6 k-steps, hoisted) ----
    uint32_t afr[6][4];
    {
        int q = lane >> 3, r = lane & 7;
        uint32_t abase = sbase + ((w & 7) * 16 + (q & 1) * 8 + r) * 208 + (q >> 1) * 16;
        #pragma unroll
        for (int kk = 0; kk < 6; kk++) ldsm4(afr[kk], abase + kk * 32);
    }

    uint32_t brow_off;
    {
        int q = lane >> 3, r = lane & 7;
        brow_off = (uint32_t)((nh * 32 + (q >> 1) * 8 + r) * 208 + (q & 1) * 16);
    }

    float v1a = -3e38f, v2a = -3e38f, v1b = -3e38f, v2b = -3e38f;
    int   i1a = 0, i2a = 0, i1b = 0, i2b = 0;

    #define UPD(V1, I1, V2, I2, val, idx)                                     \
        if ((val) > V2) {                                                     \
            if ((val) > V1) { V2 = V1; I2 = I1; V1 = (val); I1 = (idx); }     \
            else            { V2 = (val); I2 = (idx); }                       \
        }

    for (int t = 0; t < 256; t++) {
        CP_WAIT0();
        __syncthreads();
        if (t + 1 < 256) {
            const char* src = ebase + (size_t)(t + 1) * 64 * 192;
            uint32_t dst = sbase + A_BYTES + ((t + 1) & 1) * B_BYTES;
            for (int ci = tid; ci < 768; ci += 512)
                cpasync16(dst + (ci / 12) * 208 + (ci % 12) * 16,
                          src + (ci / 12) * 192 + (ci % 12) * 16);
            CP_COMMIT();
        }

        uint32_t bb = sbase + A_BYTES + (t & 1) * B_BYTES + brow_off;
        float acc[4][4];
        #pragma unroll
        for (int nb = 0; nb < 4; nb++)
            #pragma unroll
            for (int i = 0; i < 4; i++) acc[nb][i] = 0.f;

        #pragma unroll
        for (int kk = 0; kk < 6; kk++) {
            #pragma unroll
            for (int j = 0; j < 2; j++) {
                uint32_t br[4];
                ldsm4(br, bb + j * (16 * 208) + kk * 32);
                mma16816(acc[2 * j],     afr[kk], br);
                mma16816(acc[2 * j + 1], afr[kk], br + 2);
            }
        }

        int cb = t * 64 + nh * 32 + 2 * tg;
        #pragma unroll
        for (int nb = 0; nb < 4; nb++) {
            int c = cb + nb * 8;
            UPD(v1a, i1a, v2a, i2a, acc[nb][0], c);
            UPD(v1a, i1a, v2a, i2a, acc[nb][1], c + 1);
            UPD(v1b, i1b, v2b, i2b, acc[nb][2], c);
            UPD(v1b, i1b, v2b, i2b, acc[nb][3], c + 1);
        }
    }

    // ---- merge across the 4 lanes sharing a row (tg dimension) ----
    #define QMERGE(V1, I1, V2, I2, off)                                        \
    {                                                                          \
        float ov1 = __shfl_xor_sync(0xffffffffu, V1, off);                     \
        int   oi1 = __shfl_xor_sync(0xffffffffu, I1, off);                     \
        float ov2 = __shfl_xor_sync(0xffffffffu, V2, off);                     \
        int   oi2 = __shfl_xor_sync(0xffffffffu, I2, off);                     \
        if (better(ov1, oi1, V1, I1)) {                                       \
            if (better(V1, I1, ov2, oi2)) { V2 = V1; I2 = I1; }               \
            else                          { V2 = ov2; I2 = oi2; }             \
            V1 = ov1; I1 = oi1;                                               \
        } else if (better(ov1, oi1, V2, I2)) { V2 = ov1; I2 = oi1; }          \
    }
    QMERGE(v1a, i1a, v2a, i2a, 1); QMERGE(v1a, i1a, v2a, i2a, 2);
    QMERGE(v1b, i1b, v2b, i2b, 1); QMERGE(v1b, i1b, v2b, i2b, 2);

    // ---- cross-half merge via SMEM (reuse B region) ----
    __syncthreads();
    float* sv = (float*)(sm + A_BYTES);
    int*   si = (int*)(sm + A_BYTES);
    if (tg == 0) {
        int posA = (w & 7) * 16 + gr;
        int ia = (posA * 2 + nh) * 4;
        int ib = ((posA + 8) * 2 + nh) * 4;
        sv[ia] = v1a; si[ia + 1] = i1a; sv[ia + 2] = v2a; si[ia + 3] = i2a;
        sv[ib] = v1b; si[ib + 1] = i1b; sv[ib + 2] = v2b; si[ib + 3] = i2b;
    }
    __syncthreads();
    if (tid < 128) {
        int h0 = (tid * 2) * 4, h1 = (tid * 2 + 1) * 4;
        float v1 = sv[h0], v2 = sv[h0 + 2];
        int   i1 = si[h0 + 1], i2 = si[h0 + 3];
        float ov1 = sv[h1], ov2 = sv[h1 + 2];
        int   oi1 = si[h1 + 1], oi2 = si[h1 + 3];
        if (better(ov1, oi1, v1, i1)) {
            if (better(v1, i1, ov2, oi2)) { v2 = v1; i2 = i1; }
            else                          { v2 = ov2; i2 = oi2; }
            v1 = ov1; i1 = oi1;
        } else if (better(ov1, oi1, v2, i2)) { v2 = ov1; i2 = oi1; }
        g_top[pbase + tid] = make_int2(i1, i2);
    }
}

// ---------------------------------------------------------------------------
// K_rescore: exact fp32 dot for the two candidates; pick winner; histogram.
// ---------------------------------------------------------------------------
__global__ __launch_bounds__(256) void k_rescore() {
    int p = blockIdx.x * 256 + threadIdx.x;
    int2 tp = g_top[p];
    const float* zp = g_z + (size_t)p * Dd;
    const float* e1 = g_e + (size_t)tp.x * Dd;
    const float* e2 = g_e + (size_t)tp.y * Dd;
    float s1 = 0.f, s2 = 0.f;
    #pragma unroll
    for (int d = 0; d < Dd; d++) {
        float zz = zp[d];
        s1 += zz * e1[d];
        s2 += zz * e2[d];
    }
    int pick = (s2 > s1 || (s2 == s1 && tp.y < tp.x)) ? tp.y : tp.x;
    g_idx[p] = pick;
    atomicAdd(&g_hist[pick], 1);
}

// ---------------------------------------------------------------------------
// K3: gather latents, quantization-loss partial, expand D->C, write out.
// ---------------------------------------------------------------------------
__global__ __launch_bounds__(256) void k_output(const float* __restrict__ ew,
                                                const float* __restrict__ eb,
                                                float* __restrict__ out) {
    __shared__ float lat_s[32][33];
    __shared__ float exp_s[64][32];
    __shared__ float red[256];

    int bh  = blockIdx.x;
    int b   = bh >> 5, h = bh & 31;
    int tid = threadIdx.x;
    int pbase = bh * 32;

    float lsum = 0.f;
    for (int i = tid; i < 1024; i += 256) {
        int ww = i >> 5, d = i & 31;
        int ix = g_idx[pbase + ww];
        float lv = g_e[(size_t)ix * Dd + d];
        lat_s[ww][d] = lv;
        float dz = g_z[((size_t)pbase + ww) * Dd + d] - lv;
        lsum += dz * dz;
    }
    red[tid] = lsum;
    __syncthreads();
    for (int s = 128; s; s >>= 1) {
        if (tid < s) red[tid] += red[tid + s];
        __syncthreads();
    }
    if (tid == 0) g_loss_part[bh] = red[0];

    int w   = tid & 31;
    int cg8 = tid >> 5;

    for (int c0 = 0; c0 < Cc; c0 += 64) {
        __syncthreads();
        for (int i = tid; i < 64 * 32; i += 256) {
            int cl = i >> 5, d = i & 31;
            exp_s[cl][d] = ew[(size_t)(c0 + cl) * Dd + d];
        }
        __syncthreads();
        #pragma unroll
        for (int jj = 0; jj < 8; jj++) {
            int cl = cg8 + 8 * jj;
            int c  = c0 + cl;
            float s = eb[c];
            #pragma unroll
            for (int d = 0; d < 32; d++) s += exp_s[cl][d] * lat_s[w][d];
            out[(((size_t)b * Cc + c) * Hh + h) * Ww + w] = s;
        }
    }
}

// ---------------------------------------------------------------------------
// K4: final scalars — loss mean and perplexity.
// ---------------------------------------------------------------------------
__global__ void k_scalars(float* __restrict__ out, int osz) {
    __shared__ float red[256];
    int tid = threadIdx.x;

    float s = 0.f;
    for (int i = tid; i < 512; i += 256) s += g_loss_part[i];
    red[tid] = s;
    __syncthreads();
    for (int st = 128; st; st >>= 1) {
        if (tid < st) red[tid] += red[tid + st];
        __syncthreads();
    }
    if (tid == 0) out[osz - 2] = red[0] / (float)(Pp * Dd);
    __syncthreads();

    float e = 0.f;
    const float inv = 1.0f / (float)Pp;
    for (int i = tid; i < Nn; i += 256) {
        int c = g_hist[i];
        if (c > 0) {
            float u = (float)c * inv;
            e -= u * logf(u + 1e-6f);
        }
    }
    red[tid] = e;
    __syncthreads();
    for (int st = 128; st; st >>= 1) {
        if (tid < st) red[tid] += red[tid + st];
        __syncthreads();
    }
    if (tid == 0) out[osz - 1] = expf(red[0]);
}

// ---------------------------------------------------------------------------
extern "C" void kernel_launch(void* const* d_in, const int* in_sizes, int n_in,
                              void* d_out, int out_size) {
    const float* enc = (const float*)d_in[0];   // encodings [B,C,H,W]
    const float* emb = (const float*)d_in[1];   // emb_weight [N,D]
    const float* pw  = (const float*)d_in[2];   // proj_w [D,C]
    const float* pb  = (const float*)d_in[3];   // proj_b [D]
    const float* ew  = (const float*)d_in[4];   // exp_w [C,D]
    const float* eb  = (const float*)d_in[5];   // exp_b [C]
    float* out = (float*)d_out;

    cudaFuncSetAttribute(k_sims, cudaFuncAttributeMaxDynamicSharedMemorySize, SIMS_SMEM);

    k_zero_hist<<<Nn / 256, 256>>>();
    k_prep_e<<<Nn / 8, 256>>>(emb);
    k_project<<<Bb * Hh, 256>>>(enc, pw, pb);
    k_sims<<<Pp / 128, 512, SIMS_SMEM>>>();
    k_rescore<<<Pp / 256, 256>>>();
    k_output<<<Bb * Hh, 256>>>(ew, eb, out);
    k_scalars<<<1, 256>>>(out, out_size);
}

// round 5
// speedup vs baseline: 1.4389x; 1.1960x over previous
#include <cuda_runtime.h>
#include <cuda_bf16.h>
#include <math.h>
#include <cstdint>

#define Bb 16
#define Cc 512
#define Hh 32
#define Ww 32
#define Nn 16384
#define Dd 32
#define Pp 16384   // Bb*Hh*Ww

// ---------------------------------------------------------------------------
// Scratch (__device__ globals; no allocation allowed)
// ---------------------------------------------------------------------------
__device__ float g_z[Pp * Dd];        // normalized projected latents [p][d]
__device__ float g_e[Nn * Dd];        // normalized codebook fp32 [n][d]
__device__ uint4 g_eb[Nn * 12];       // codebook bf16 split: [n][96 bf16] = [hi|mid|hi]
__device__ float g_tmax[(size_t)Pp * 512];  // per-position per-32-code-entry max
__device__ int   g_idx[Pp];
__device__ int   g_hist[Nn];
__device__ float g_loss_part[512];

// ---------------------------------------------------------------------------
// PTX helpers (baseline PTX only: no 'a'-features)
// ---------------------------------------------------------------------------
__device__ __forceinline__ uint32_t smem_u32(const void* p) {
    uint32_t a;
    asm("{ .reg .u64 t; cvta.to.shared.u64 t, %1; cvt.u32.u64 %0, t; }" : "=r"(a) : "l"(p));
    return a;
}
__device__ __forceinline__ void ldsm4(uint32_t* r, uint32_t addr) {
    asm volatile("ldmatrix.sync.aligned.m8n8.x4.shared.b16 {%0,%1,%2,%3}, [%4];"
                 : "=r"(r[0]), "=r"(r[1]), "=r"(r[2]), "=r"(r[3]) : "r"(addr));
}
__device__ __forceinline__ void mma16816(float* d, const uint32_t* a, const uint32_t* b) {
    asm volatile("mma.sync.aligned.m16n8k16.row.col.f32.bf16.bf16.f32 "
                 "{%0,%1,%2,%3}, {%4,%5,%6,%7}, {%8,%9}, {%0,%1,%2,%3};"
                 : "+f"(d[0]), "+f"(d[1]), "+f"(d[2]), "+f"(d[3])
                 : "r"(a[0]), "r"(a[1]), "r"(a[2]), "r"(a[3]), "r"(b[0]), "r"(b[1]));
}
__device__ __forceinline__ void cpasync16(uint32_t dst, const void* src) {
    asm volatile("cp.async.cg.shared.global [%0], [%1], 16;" :: "r"(dst), "l"(src));
}
#define CP_COMMIT() asm volatile("cp.async.commit_group;" ::: "memory")
#define CP_WAIT0()  asm volatile("cp.async.wait_group 0;" ::: "memory")

__device__ __forceinline__ bool better(float xv, int xi, float yv, int yi) {
    return xv > yv || (xv == yv && xi < yi);
}

// ---------------------------------------------------------------------------
// K_zero: clear histogram
// ---------------------------------------------------------------------------
__global__ void k_zero_hist() {
    g_hist[blockIdx.x * 256 + threadIdx.x] = 0;
}

// ---------------------------------------------------------------------------
// K_prep_e: normalize codebook rows; fp32 copy + bf16 split [hi|mid|hi].
// ---------------------------------------------------------------------------
__global__ void k_prep_e(const float* __restrict__ emb) {
    int warp = threadIdx.x >> 5, lane = threadIdx.x & 31;
    int n = blockIdx.x * 8 + warp;
    float v = emb[n * Dd + lane];
    float ss = v * v;
    #pragma unroll
    for (int o = 16; o; o >>= 1) ss += __shfl_xor_sync(0xffffffffu, ss, o);
    float rn = 1.0f / fmaxf(sqrtf(ss), 1e-6f);
    float zn = v * rn;
    g_e[n * Dd + lane] = zn;

    __nv_bfloat16 h = __float2bfloat16(zn);
    __nv_bfloat16 m = __float2bfloat16(zn - __bfloat162float(h));
    __nv_bfloat16* gb = (__nv_bfloat16*)g_eb + (size_t)n * 96 + lane;
    gb[0]  = h;    // k-block 0: e_hi
    gb[32] = m;    // k-block 1: e_mid
    gb[64] = h;    // k-block 2: e_hi
}

// ---------------------------------------------------------------------------
// K1: projection (1x1 conv C->D) + L2 normalize along D.
// ---------------------------------------------------------------------------
__global__ __launch_bounds__(256) void k_project(const float* __restrict__ enc,
                                                 const float* __restrict__ pw,
                                                 const float* __restrict__ pb) {
    __shared__ float enc_s[64][32];
    __shared__ float proj_s[32][64];
    __shared__ float z_s[32][33];
    __shared__ float rn_s[32];

    int bh  = blockIdx.x;
    int tid = threadIdx.x;
    int w   = tid & 31;
    int dg  = tid >> 5;

    const float* encbase = enc + (size_t)(bh >> 5) * Cc * Hh * Ww + (size_t)(bh & 31) * Ww;

    float acc[4] = {0.f, 0.f, 0.f, 0.f};

    for (int c0 = 0; c0 < Cc; c0 += 64) {
        for (int i = tid; i < 64 * 32; i += 256) {
            int cl = i >> 5, ww = i & 31;
            enc_s[cl][ww] = encbase[(size_t)(c0 + cl) * (Hh * Ww) + ww];
        }
        for (int i = tid; i < 32 * 64; i += 256) {
            int d = i >> 6, cl = i & 63;
            proj_s[d][cl] = pw[d * Cc + c0 + cl];
        }
        __syncthreads();
        #pragma unroll 16
        for (int cl = 0; cl < 64; cl++) {
            float ev = enc_s[cl][w];
            #pragma unroll
            for (int j = 0; j < 4; j++) acc[j] += proj_s[dg + 8 * j][cl] * ev;
        }
        __syncthreads();
    }
    #pragma unroll
    for (int j = 0; j < 4; j++) z_s[dg + 8 * j][w] = acc[j] + pb[dg + 8 * j];
    __syncthreads();

    if (tid < 32) {
        float ss = 0.f;
        #pragma unroll
        for (int d = 0; d < 32; d++) { float v = z_s[d][tid]; ss += v * v; }
        rn_s[tid] = 1.0f / fmaxf(sqrtf(ss), 1e-6f);
    }
    __syncthreads();

    for (int i = tid; i < 1024; i += 256) {
        int ww = i >> 5, d = i & 31;
        g_z[((size_t)bh * 32 + ww) * Dd + d] = z_s[d][ww] * rn_s[ww];
    }
}

// ---------------------------------------------------------------------------
// K2: HMMA sims (bf16 3-split, K=96); per-position per-32-code-entry MAX only.
// CTA: 512 threads (16 warps), 128 positions. Code tile = 128, 128 tiles.
// Warp (w&7): row group (16 pos); (w>>3): n-half (64 codes of the tile).
// Entry e = t*4 + nh*2 + hf covers codes [32e, 32e+32).
// SMEM: A 128x104 bf16 (26624 B); B double buffer 2 x 128x104 bf16.
// ---------------------------------------------------------------------------
#define A_BYTES   26624
#define B_BYTES   26624
#define SIMS_SMEM (A_BYTES + 2 * B_BYTES)   // 79872

__global__ __launch_bounds__(512, 1) void k_sims() {
    extern __shared__ __align__(16) char sm[];
    __nv_bfloat16* As = (__nv_bfloat16*)sm;     // stride 104 bf16 = 208 B
    uint32_t sbase = smem_u32(sm);

    int tid  = threadIdx.x;
    int lane = tid & 31;
    int w    = tid >> 5;
    int nh   = w >> 3;        // n-half (64 codes)
    int tg   = lane & 3;
    int gr   = lane >> 2;     // row-in-group 0..7
    int pbase = blockIdx.x * 128;

    // ---- build A tile: [hi | hi | mid] per row ----
    for (int i = tid; i < 128 * 32; i += 512) {
        int row = i >> 5, d = i & 31;
        float z = g_z[(size_t)(pbase + row) * Dd + d];
        __nv_bfloat16 h = __float2bfloat16(z);
        __nv_bfloat16 m = __float2bfloat16(z - __bfloat162float(h));
        As[row * 104 + d]      = h;
        As[row * 104 + 32 + d] = h;
        As[row * 104 + 64 + d] = m;
    }

    // ---- precompute cp.async chunk addressing (3 chunks/thread/tile) ----
    // B tile = 128 codes x 192 B = 1536 x 16B chunks.
    uint32_t srcOff[3], dstOff[3];
    #pragma unroll
    for (int k = 0; k < 3; k++) {
        int ci  = tid + 512 * k;
        int row = ci / 12, seg = ci % 12;
        srcOff[k] = (uint32_t)(row * 192 + seg * 16);
        dstOff[k] = (uint32_t)(row * 208 + seg * 16);
    }

    // ---- prefetch B tile 0 ----
    const char* ebase = (const char*)g_eb;
    #pragma unroll
    for (int k = 0; k < 3; k++)
        cpasync16(sbase + A_BYTES + dstOff[k], ebase + srcOff[k]);
    CP_COMMIT();
    __syncthreads();

    // ---- A fragments (all 6 k-steps, hoisted) ----
    uint32_t afr[6][4];
    {
        int q = lane >> 3, r = lane & 7;
        uint32_t abase = sbase + ((w & 7) * 16 + (q & 1) * 8 + r) * 208 + (q >> 1) * 16;
        #pragma unroll
        for (int kk = 0; kk < 6; kk++) ldsm4(afr[kk], abase + kk * 32);
    }

    uint32_t brow_off;
    {
        int q = lane >> 3, r = lane & 7;
        brow_off = (uint32_t)((nh * 64 + (q >> 1) * 8 + r) * 208 + (q & 1) * 16);
    }

    for (int t = 0; t < 128; t++) {
        CP_WAIT0();
        __syncthreads();
        if (t + 1 < 128) {
            const char* src = ebase + (size_t)(t + 1) * 24576;
            uint32_t dst = sbase + A_BYTES + ((t + 1) & 1) * B_BYTES;
            #pragma unroll
            for (int k = 0; k < 3; k++)
                cpasync16(dst + dstOff[k], src + srcOff[k]);
            CP_COMMIT();
        }

        uint32_t bb = sbase + A_BYTES + (t & 1) * B_BYTES + brow_off;
        float acc[8][4];
        #pragma unroll
        for (int nb = 0; nb < 8; nb++)
            #pragma unroll
            for (int i = 0; i < 4; i++) acc[nb][i] = 0.f;

        #pragma unroll
        for (int kk = 0; kk < 6; kk++) {
            #pragma unroll
            for (int j = 0; j < 4; j++) {
                uint32_t br[4];
                ldsm4(br, bb + j * (16 * 208) + kk * 32);
                mma16816(acc[2 * j],     afr[kk], br);
                mma16816(acc[2 * j + 1], afr[kk], br + 2);
            }
        }

        // ---- per-entry max (value only, FMNMX trees + shfl) ----
        // posA = (w&7)*16 + gr ; posB = posA + 8
        // half hf: nb 0..3 (codes +0..31), nb 4..7 (codes +32..63)
        float mA0, mA1, mB0, mB1;
        {
            float a0 = fmaxf(fmaxf(acc[0][0], acc[0][1]), fmaxf(acc[1][0], acc[1][1]));
            float a1 = fmaxf(fmaxf(acc[2][0], acc[2][1]), fmaxf(acc[3][0], acc[3][1]));
            mA0 = fmaxf(a0, a1);
            float a2 = fmaxf(fmaxf(acc[4][0], acc[4][1]), fmaxf(acc[5][0], acc[5][1]));
            float a3 = fmaxf(fmaxf(acc[6][0], acc[6][1]), fmaxf(acc[7][0], acc[7][1]));
            mA1 = fmaxf(a2, a3);
            float b0 = fmaxf(fmaxf(acc[0][2], acc[0][3]), fmaxf(acc[1][2], acc[1][3]));
            float b1 = fmaxf(fmaxf(acc[2][2], acc[2][3]), fmaxf(acc[3][2], acc[3][3]));
            mB0 = fmaxf(b0, b1);
            float b2 = fmaxf(fmaxf(acc[4][2], acc[4][3]), fmaxf(acc[5][2], acc[5][3]));
            float b3 = fmaxf(fmaxf(acc[6][2], acc[6][3]), fmaxf(acc[7][2], acc[7][3]));
            mB1 = fmaxf(b2, b3);
        }
        mA0 = fmaxf(mA0, __shfl_xor_sync(0xffffffffu, mA0, 1));
        mA0 = fmaxf(mA0, __shfl_xor_sync(0xffffffffu, mA0, 2));
        mA1 = fmaxf(mA1, __shfl_xor_sync(0xffffffffu, mA1, 1));
        mA1 = fmaxf(mA1, __shfl_xor_sync(0xffffffffu, mA1, 2));
        mB0 = fmaxf(mB0, __shfl_xor_sync(0xffffffffu, mB0, 1));
        mB0 = fmaxf(mB0, __shfl_xor_sync(0xffffffffu, mB0, 2));
        mB1 = fmaxf(mB1, __shfl_xor_sync(0xffffffffu, mB1, 1));
        mB1 = fmaxf(mB1, __shfl_xor_sync(0xffffffffu, mB1, 2));

        if (tg == 0) {
            int posA = (w & 7) * 16 + gr;
            size_t ba = (size_t)(pbase + posA) * 512 + t * 4 + nh * 2;
            g_tmax[ba]     = mA0;
            g_tmax[ba + 1] = mA1;
            size_t bbx = ba + (size_t)8 * 512;    // posB = posA + 8
            g_tmax[bbx]     = mB0;
            g_tmax[bbx + 1] = mB1;
        }
    }
}

// ---------------------------------------------------------------------------
// K_pass2: per position, scan 512 entry maxima -> top-2 entries;
// exact fp32 rescore of their 64 codes; write argmax + histogram.
// One warp per position; 8 positions per block.
// ---------------------------------------------------------------------------
__global__ __launch_bounds__(256) void k_pass2() {
    __shared__ float zs[8][32];
    int tid  = threadIdx.x;
    int wp   = tid >> 5;
    int lane = tid & 31;
    int p    = blockIdx.x * 8 + wp;

    zs[wp][lane] = g_z[(size_t)p * Dd + lane];
    __syncwarp();

    // top-2 entries (approx values, tie -> smaller entry id)
    const float4* tm = (const float4*)(g_tmax + (size_t)p * 512 + lane * 16);
    float v1 = -3e38f, v2 = -3e38f;
    int   e1 = 0, e2 = 0;
    #pragma unroll
    for (int q = 0; q < 4; q++) {
        float4 f = tm[q];
        float vv[4] = {f.x, f.y, f.z, f.w};
        #pragma unroll
        for (int j = 0; j < 4; j++) {
            int ei = lane * 16 + q * 4 + j;
            if (vv[j] > v2) {
                if (vv[j] > v1) { v2 = v1; e2 = e1; v1 = vv[j]; e1 = ei; }
                else            { v2 = vv[j]; e2 = ei; }
            }
        }
    }
    #pragma unroll
    for (int o = 16; o; o >>= 1) {
        float ov1 = __shfl_xor_sync(0xffffffffu, v1, o);
        int   oe1 = __shfl_xor_sync(0xffffffffu, e1, o);
        float ov2 = __shfl_xor_sync(0xffffffffu, v2, o);
        int   oe2 = __shfl_xor_sync(0xffffffffu, e2, o);
        if (better(ov1, oe1, v1, e1)) {
            if (better(v1, e1, ov2, oe2)) { v2 = v1; e2 = e1; }
            else                          { v2 = ov2; e2 = oe2; }
            v1 = ov1; e1 = oe1;
        } else if (better(ov1, oe1, v2, e2)) { v2 = ov1; e2 = oe1; }
    }

    // exact rescore: codes 32*e1 + lane, 32*e2 + lane
    int c1 = e1 * 32 + lane;
    int c2 = e2 * 32 + lane;
    const float* ea = g_e + (size_t)c1 * Dd;
    const float* eb2 = g_e + (size_t)c2 * Dd;
    float s1 = 0.f, s2 = 0.f;
    #pragma unroll
    for (int d = 0; d < Dd; d++) {
        float zd = zs[wp][d];
        s1 += zd * ea[d];
        s2 += zd * eb2[d];
    }
    float bv; int bi;
    if (better(s1, c1, s2, c2)) { bv = s1; bi = c1; }
    else                        { bv = s2; bi = c2; }
    #pragma unroll
    for (int o = 16; o; o >>= 1) {
        float ov = __shfl_xor_sync(0xffffffffu, bv, o);
        int   oi = __shfl_xor_sync(0xffffffffu, bi, o);
        if (better(ov, oi, bv, bi)) { bv = ov; bi = oi; }
    }
    if (lane == 0) {
        g_idx[p] = bi;
        atomicAdd(&g_hist[bi], 1);
    }
}

// ---------------------------------------------------------------------------
// K3: gather latents, quantization-loss partial, expand D->C, write out.
// ---------------------------------------------------------------------------
__global__ __launch_bounds__(256) void k_output(const float* __restrict__ ew,
                                                const float* __restrict__ eb,
                                                float* __restrict__ out) {
    __shared__ float lat_s[32][33];
    __shared__ float exp_s[64][32];
    __shared__ float red[256];

    int bh  = blockIdx.x;
    int b   = bh >> 5, h = bh & 31;
    int tid = threadIdx.x;
    int pbase = bh * 32;

    float lsum = 0.f;
    for (int i = tid; i < 1024; i += 256) {
        int ww = i >> 5, d = i & 31;
        int ix = g_idx[pbase + ww];
        float lv = g_e[(size_t)ix * Dd + d];
        lat_s[ww][d] = lv;
        float dz = g_z[((size_t)pbase + ww) * Dd + d] - lv;
        lsum += dz * dz;
    }
    red[tid] = lsum;
    __syncthreads();
    for (int s = 128; s; s >>= 1) {
        if (tid < s) red[tid] += red[tid + s];
        __syncthreads();
    }
    if (tid == 0) g_loss_part[bh] = red[0];

    int w   = tid & 31;
    int cg8 = tid >> 5;

    for (int c0 = 0; c0 < Cc; c0 += 64) {
        __syncthreads();
        for (int i = tid; i < 64 * 32; i += 256) {
            int cl = i >> 5, d = i & 31;
            exp_s[cl][d] = ew[(size_t)(c0 + cl) * Dd + d];
        }
        __syncthreads();
        #pragma unroll
        for (int jj = 0; jj < 8; jj++) {
            int cl = cg8 + 8 * jj;
            int c  = c0 + cl;
            float s = eb[c];
            #pragma unroll
            for (int d = 0; d < 32; d++) s += exp_s[cl][d] * lat_s[w][d];
            out[(((size_t)b * Cc + c) * Hh + h) * Ww + w] = s;
        }
    }
}

// ---------------------------------------------------------------------------
// K4: final scalars — loss mean and perplexity.
// ---------------------------------------------------------------------------
__global__ void k_scalars(float* __restrict__ out, int osz) {
    __shared__ float red[256];
    int tid = threadIdx.x;

    float s = 0.f;
    for (int i = tid; i < 512; i += 256) s += g_loss_part[i];
    red[tid] = s;
    __syncthreads();
    for (int st = 128; st; st >>= 1) {
        if (tid < st) red[tid] += red[tid + st];
        __syncthreads();
    }
    if (tid == 0) out[osz - 2] = red[0] / (float)(Pp * Dd);
    __syncthreads();

    float e = 0.f;
    const float inv = 1.0f / (float)Pp;
    for (int i = tid; i < Nn; i += 256) {
        int c = g_hist[i];
        if (c > 0) {
            float u = (float)c * inv;
            e -= u * logf(u + 1e-6f);
        }
    }
    red[tid] = e;
    __syncthreads();
    for (int st = 128; st; st >>= 1) {
        if (tid < st) red[tid] += red[tid + st];
        __syncthreads();
    }
    if (tid == 0) out[osz - 1] = expf(red[0]);
}

// ---------------------------------------------------------------------------
extern "C" void kernel_launch(void* const* d_in, const int* in_sizes, int n_in,
                              void* d_out, int out_size) {
    const float* enc = (const float*)d_in[0];   // encodings [B,C,H,W]
    const float* emb = (const float*)d_in[1];   // emb_weight [N,D]
    const float* pw  = (const float*)d_in[2];   // proj_w [D,C]
    const float* pb  = (const float*)d_in[3];   // proj_b [D]
    const float* ew  = (const float*)d_in[4];   // exp_w [C,D]
    const float* eb  = (const float*)d_in[5];   // exp_b [C]
    float* out = (float*)d_out;

    cudaFuncSetAttribute(k_sims, cudaFuncAttributeMaxDynamicSharedMemorySize, SIMS_SMEM);

    k_zero_hist<<<Nn / 256, 256>>>();
    k_prep_e<<<Nn / 8, 256>>>(emb);
    k_project<<<Bb * Hh, 256>>>(enc, pw, pb);
    k_sims<<<Pp / 128, 512, SIMS_SMEM>>>();
    k_pass2<<<Pp / 8, 256>>>();
    k_output<<<Bb * Hh, 256>>>(ew, eb, out);
    k_scalars<<<1, 256>>>(out, out_size);
}